// round 6
// baseline (speedup 1.0000x reference)
#include <cuda_runtime.h>
#include <cstdint>

// Problem constants
#define NN 50000
#define EE 800000
#define F_IN 128
#define HDIM 256

// ---------------- scratch (static device memory) ------------------------------
__device__ float g_r  [(size_t)EE * HDIM];   // layer-2 intermediate r
__device__ float g_inv[NN];
__device__ float g_h1 [(size_t)NN * HDIM];
__device__ float g_hN [(size_t)NN * HDIM];
__device__ float g_cnt[NN];
// transposed weights: Wt[n,k] (K-major rows)
__device__ float g_wr1a[F_IN * F_IN];
__device__ float g_wr1b[F_IN * F_IN];
__device__ float g_wl1 [HDIM * 2 * F_IN];
__device__ float g_we2 [HDIM * F_IN];
__device__ float g_wr2a[HDIM * HDIM];
__device__ float g_wr2b[HDIM * HDIM];

// ---------------- helpers ------------------------------------------------------
__device__ __forceinline__ uint32_t f2tf32(float f) {
    uint32_t r; asm("cvt.rna.tf32.f32 %0, %1;" : "=r"(r) : "f"(f)); return r;
}
__device__ __forceinline__ void mma_tf32(float& d0, float& d1, float& d2, float& d3,
                                         uint32_t a0, uint32_t a1, uint32_t a2, uint32_t a3,
                                         uint32_t b0, uint32_t b1) {
    asm volatile(
        "mma.sync.aligned.m16n8k8.row.col.f32.tf32.tf32.f32 "
        "{%0,%1,%2,%3}, {%4,%5,%6,%7}, {%8,%9}, {%0,%1,%2,%3};\n"
        : "+f"(d0), "+f"(d1), "+f"(d2), "+f"(d3)
        : "r"(a0), "r"(a1), "r"(a2), "r"(a3), "r"(b0), "r"(b1));
}

#define SS 36            // padded float stride per 32-wide K chunk
#define SZC (128 * SS)   // floats per 128-row chunk

// ---------------- small utility kernels ---------------------------------------
__global__ void k_zero(float* __restrict__ p, int n) {
    int i = blockIdx.x * blockDim.x + threadIdx.x;
    if (i < n) p[i] = 0.f;
}
__global__ void k_degree(const int* __restrict__ dst, float* __restrict__ cnt, int E) {
    int e = blockIdx.x * blockDim.x + threadIdx.x;
    if (e < E) atomicAdd(&cnt[dst[e]], 1.f);
}
__global__ void k_invn(const float* __restrict__ h, float* __restrict__ inv, int Nn, int F) {
    int gw   = (blockIdx.x * blockDim.x + threadIdx.x) >> 5;
    int lane = threadIdx.x & 31;
    if (gw >= Nn) return;
    const float* row = h + (size_t)gw * F;
    float s = 0.f;
    for (int k = lane; k < F; k += 32) { float v = row[k]; s += v * v; }
    #pragma unroll
    for (int o = 16; o; o >>= 1) s += __shfl_xor_sync(0xFFFFFFFFu, s, o);
    if (lane == 0) inv[gw] = 1.f / fmaxf(sqrtf(s), 1e-12f);
}
__global__ void k_div(float* __restrict__ hN, const float* __restrict__ cnt, int Nn, int F) {
    int i = blockIdx.x * blockDim.x + threadIdx.x;
    if (i < Nn * F) hN[i] /= fmaxf(cnt[i / F], 1.f);
}
__global__ void k_tr(const float* __restrict__ W, float* __restrict__ Wt, int K, int N) {
    __shared__ float s[32][33];
    int bx = blockIdx.x * 32, by = blockIdx.y * 32;
    int x = threadIdx.x, y = threadIdx.y;
    #pragma unroll
    for (int j = 0; j < 32; j += 8) s[y + j][x] = W[(size_t)(by + y + j) * N + bx + x];
    __syncthreads();
    #pragma unroll
    for (int j = 0; j < 32; j += 8) Wt[(size_t)(bx + y + j) * K + by + x] = s[x][y + j];
}

// ===================== LAYER-1 MEGA KERNEL ====================================
// block = 128 edges. cos -> m tile (smem tf32) -> GEMM x Wr1a (relu->smem)
// -> GEMM x Wr1b (relu -> atomic scatter into hN[dst]).
__global__ __launch_bounds__(256, 1)
void k_l1(const float* __restrict__ hf, const int* __restrict__ src,
          const int* __restrict__ dst, const float* __restrict__ inv,
          const float* __restrict__ ef,
          const float* __restrict__ We1, const float* __restrict__ be1,
          const float* __restrict__ w1a, const float* __restrict__ b1a,
          const float* __restrict__ w1b, const float* __restrict__ b1b,
          float* __restrict__ hN) {
    extern __shared__ float sm[];
    float* sm_m = sm;                 // 4 chunks: m tile
    float* sm_r = sm_m + 4 * SZC;     // 4 chunks: r tile
    float* sm_b = sm_r + 4 * SZC;     // 1 chunk: B staging (128 rows)
    __shared__ int   s_src[128], s_dst[128];
    __shared__ float s_ef[256], s_cos[128];
    __shared__ float s_w0[128], s_w1[128], s_wb[128], s_ba[128], s_bb[128];

    const int tid = threadIdx.x, wid = tid >> 5, lane = tid & 31;
    const int wm = wid & 1, wn = wid >> 1, lr = lane >> 2, lc = lane & 3;
    const int e0 = blockIdx.x * 128;

    for (int i = tid; i < 128; i += 256) {
        s_src[i] = src[e0 + i]; s_dst[i] = dst[e0 + i];
        s_w0[i] = We1[i]; s_w1[i] = We1[128 + i]; s_wb[i] = be1[i];
        s_ba[i] = b1a[i]; s_bb[i] = b1b[i];
    }
    s_ef[tid] = ef[(size_t)e0 * 2 + tid];
    __syncthreads();

    // cosine: warp handles 16 edges
    #pragma unroll 1
    for (int t = 0; t < 16; t++) {
        int e = wid * 16 + t;
        int s = s_src[e], d = s_dst[e];
        float4 a = ((const float4*)(hf + (size_t)s * 128))[lane];
        float4 b = ((const float4*)(hf + (size_t)d * 128))[lane];
        float p = a.x * b.x + a.y * b.y + a.z * b.z + a.w * b.w;
        #pragma unroll
        for (int o = 16; o; o >>= 1) p += __shfl_xor_sync(0xFFFFFFFFu, p, o);
        if (lane == 0) s_cos[e] = p * inv[s] * inv[d];
    }
    __syncthreads();

    // build m tile in tf32: m[e,c] = cos*w(e,c)*h[src,c]
    for (int i = tid; i < 128 * 128; i += 256) {
        int e = i >> 7, c = i & 127;
        float w = s_ef[2 * e] * s_w0[c] + s_ef[2 * e + 1] * s_w1[c] + s_wb[c];
        float a = hf[(size_t)s_src[e] * 128 + c];
        sm_m[(c >> 5) * SZC + e * SS + (c & 31)] =
            __uint_as_float(f2tf32(s_cos[e] * w * a));
    }

    // ---------------- GEMM1: m @ Wr1a' -----------------
    float acc[4][4][4];
    #pragma unroll
    for (int a = 0; a < 4; a++)
        #pragma unroll
        for (int b = 0; b < 4; b++)
            #pragma unroll
            for (int q = 0; q < 4; q++) acc[a][b][q] = 0.f;

    for (int ch = 0; ch < 4; ch++) {
        __syncthreads();
        #pragma unroll
        for (int i = tid; i < 1024; i += 256) {
            int n = i >> 3, c4 = i & 7;
            float4 v = *(const float4*)(w1a + (size_t)n * 128 + ch * 32 + c4 * 4);
            uint4 t4; t4.x = f2tf32(v.x); t4.y = f2tf32(v.y);
            t4.z = f2tf32(v.z); t4.w = f2tf32(v.w);
            *(uint4*)(sm_b + n * SS + c4 * 4) = t4;
        }
        __syncthreads();
        const float* As = sm_m + ch * SZC;
        #pragma unroll
        for (int kk = 0; kk < 4; kk++) {
            const int kb = kk * 8;
            uint32_t af[4][4], bf[4][2];
            #pragma unroll
            for (int mt = 0; mt < 4; mt++) {
                const int r = wm * 64 + mt * 16 + lr;
                af[mt][0] = __float_as_uint(As[(r + 0) * SS + kb + lc]);
                af[mt][1] = __float_as_uint(As[(r + 8) * SS + kb + lc]);
                af[mt][2] = __float_as_uint(As[(r + 0) * SS + kb + lc + 4]);
                af[mt][3] = __float_as_uint(As[(r + 8) * SS + kb + lc + 4]);
            }
            #pragma unroll
            for (int nt = 0; nt < 4; nt++) {
                const int n = wn * 32 + nt * 8 + lr;
                bf[nt][0] = __float_as_uint(sm_b[n * SS + kb + lc]);
                bf[nt][1] = __float_as_uint(sm_b[n * SS + kb + lc + 4]);
            }
            #pragma unroll
            for (int mt = 0; mt < 4; mt++)
                #pragma unroll
                for (int nt = 0; nt < 4; nt++)
                    mma_tf32(acc[mt][nt][0], acc[mt][nt][1], acc[mt][nt][2], acc[mt][nt][3],
                             af[mt][0], af[mt][1], af[mt][2], af[mt][3],
                             bf[nt][0], bf[nt][1]);
        }
    }
    __syncthreads();
    // epilogue1: relu -> sm_r (tf32)
    #pragma unroll
    for (int mt = 0; mt < 4; mt++)
        #pragma unroll
        for (int half = 0; half < 2; half++) {
            const int row = wm * 64 + mt * 16 + lr + half * 8;
            #pragma unroll
            for (int nt = 0; nt < 4; nt++) {
                const int col = wn * 32 + nt * 8 + lc * 2;
                float v0 = fmaxf(acc[mt][nt][half * 2 + 0] + s_ba[col], 0.f);
                float v1 = fmaxf(acc[mt][nt][half * 2 + 1] + s_ba[col + 1], 0.f);
                float* p = sm_r + (col >> 5) * SZC + row * SS + (col & 31);
                p[0] = __uint_as_float(f2tf32(v0));
                p[1] = __uint_as_float(f2tf32(v1));
            }
        }

    // ---------------- GEMM2: r @ Wr1b' -> scatter ----------------
    float ac2[4][4][4];
    #pragma unroll
    for (int a = 0; a < 4; a++)
        #pragma unroll
        for (int b = 0; b < 4; b++)
            #pragma unroll
            for (int q = 0; q < 4; q++) ac2[a][b][q] = 0.f;

    for (int ch = 0; ch < 4; ch++) {
        __syncthreads();
        #pragma unroll
        for (int i = tid; i < 1024; i += 256) {
            int n = i >> 3, c4 = i & 7;
            float4 v = *(const float4*)(w1b + (size_t)n * 128 + ch * 32 + c4 * 4);
            uint4 t4; t4.x = f2tf32(v.x); t4.y = f2tf32(v.y);
            t4.z = f2tf32(v.z); t4.w = f2tf32(v.w);
            *(uint4*)(sm_b + n * SS + c4 * 4) = t4;
        }
        __syncthreads();
        const float* As = sm_r + ch * SZC;
        #pragma unroll
        for (int kk = 0; kk < 4; kk++) {
            const int kb = kk * 8;
            uint32_t af[4][4], bf[4][2];
            #pragma unroll
            for (int mt = 0; mt < 4; mt++) {
                const int r = wm * 64 + mt * 16 + lr;
                af[mt][0] = __float_as_uint(As[(r + 0) * SS + kb + lc]);
                af[mt][1] = __float_as_uint(As[(r + 8) * SS + kb + lc]);
                af[mt][2] = __float_as_uint(As[(r + 0) * SS + kb + lc + 4]);
                af[mt][3] = __float_as_uint(As[(r + 8) * SS + kb + lc + 4]);
            }
            #pragma unroll
            for (int nt = 0; nt < 4; nt++) {
                const int n = wn * 32 + nt * 8 + lr;
                bf[nt][0] = __float_as_uint(sm_b[n * SS + kb + lc]);
                bf[nt][1] = __float_as_uint(sm_b[n * SS + kb + lc + 4]);
            }
            #pragma unroll
            for (int mt = 0; mt < 4; mt++)
                #pragma unroll
                for (int nt = 0; nt < 4; nt++)
                    mma_tf32(ac2[mt][nt][0], ac2[mt][nt][1], ac2[mt][nt][2], ac2[mt][nt][3],
                             af[mt][0], af[mt][1], af[mt][2], af[mt][3],
                             bf[nt][0], bf[nt][1]);
        }
    }
    // scatter epilogue
    #pragma unroll
    for (int mt = 0; mt < 4; mt++)
        #pragma unroll
        for (int half = 0; half < 2; half++) {
            const int row = wm * 64 + mt * 16 + lr + half * 8;
            float* cbase = hN + (size_t)s_dst[row] * 128;
            #pragma unroll
            for (int nt = 0; nt < 4; nt++) {
                const int col = wn * 32 + nt * 8 + lc * 2;
                float v0 = fmaxf(ac2[mt][nt][half * 2 + 0] + s_bb[col], 0.f);
                float v1 = fmaxf(ac2[mt][nt][half * 2 + 1] + s_bb[col + 1], 0.f);
                atomicAdd((float2*)(cbase + col), make_float2(v0, v1));
            }
        }
}

// ===================== LAYER-2 KERNEL A =======================================
// block = 128 edges. cos(h1) -> [w1 on-the-fly] GEMM x We2' -> m2 (smem) ->
// *cos*h1[src] pass -> GEMM x Wr2a' (K=256 from smem) -> relu -> write r (DRAM).
__global__ __launch_bounds__(256, 1)
void k_l2a(const float* __restrict__ h1, const int* __restrict__ src,
           const int* __restrict__ dst, const float* __restrict__ inv,
           const float* __restrict__ ef,
           const float* __restrict__ We1, const float* __restrict__ be1,
           const float* __restrict__ we2t, const float* __restrict__ be2,
           const float* __restrict__ w2a, const float* __restrict__ b2a,
           float* __restrict__ rout) {
    extern __shared__ float sm[];
    float* sm_m2 = sm;                 // 8 chunks: m2 tile (128x256)
    float* sm_a  = sm_m2 + 8 * SZC;    // 1 chunk: A staging (w1 on the fly)
    float* sm_b  = sm_a + SZC;         // B staging: 256 rows * SS
    __shared__ int   s_src[128], s_dst[128];
    __shared__ float s_ef[256], s_cos[128];
    __shared__ float s_w0[128], s_w1[128], s_wb[128];
    __shared__ float s_b2[256], s_ba[256];

    const int tid = threadIdx.x, wid = tid >> 5, lane = tid & 31;
    const int wm = wid & 1, wn = wid >> 1, lr = lane >> 2, lc = lane & 3;
    const int e0 = blockIdx.x * 128;

    for (int i = tid; i < 128; i += 256) {
        s_src[i] = src[e0 + i]; s_dst[i] = dst[e0 + i];
        s_w0[i] = We1[i]; s_w1[i] = We1[128 + i]; s_wb[i] = be1[i];
    }
    s_ef[tid] = ef[(size_t)e0 * 2 + tid];
    s_b2[tid] = be2[tid];
    s_ba[tid] = b2a[tid];
    __syncthreads();

    // cosine over h1 (256-dim)
    #pragma unroll 1
    for (int t = 0; t < 16; t++) {
        int e = wid * 16 + t;
        int s = s_src[e], d = s_dst[e];
        const float4* ps = (const float4*)(h1 + (size_t)s * 256);
        const float4* pd = (const float4*)(h1 + (size_t)d * 256);
        float p = 0.f;
        #pragma unroll
        for (int j = 0; j < 2; j++) {
            float4 a = ps[lane + 32 * j], b = pd[lane + 32 * j];
            p += a.x * b.x + a.y * b.y + a.z * b.z + a.w * b.w;
        }
        #pragma unroll
        for (int o = 16; o; o >>= 1) p += __shfl_xor_sync(0xFFFFFFFFu, p, o);
        if (lane == 0) s_cos[e] = p * inv[s] * inv[d];
    }

    // ---------------- GEMM-m2: w1 @ We2' (K=128, N=256) ----------------
    float acc[4][8][4];
    #pragma unroll
    for (int a = 0; a < 4; a++)
        #pragma unroll
        for (int b = 0; b < 8; b++)
            #pragma unroll
            for (int q = 0; q < 4; q++) acc[a][b][q] = 0.f;

    for (int ch = 0; ch < 4; ch++) {
        __syncthreads();
        // build w1 A-chunk on the fly
        #pragma unroll
        for (int i = tid; i < 128 * 32; i += 256) {
            int e = i >> 5, kc = i & 31, k = ch * 32 + kc;
            float w = fmaxf(s_ef[2 * e] * s_w0[k] + s_ef[2 * e + 1] * s_w1[k] + s_wb[k], 0.f);
            sm_a[e * SS + kc] = __uint_as_float(f2tf32(w));
        }
        // B chunk from We2' [256, 128]
        #pragma unroll
        for (int i = tid; i < 2048; i += 256) {
            int n = i >> 3, c4 = i & 7;
            float4 v = *(const float4*)(we2t + (size_t)n * 128 + ch * 32 + c4 * 4);
            uint4 t4; t4.x = f2tf32(v.x); t4.y = f2tf32(v.y);
            t4.z = f2tf32(v.z); t4.w = f2tf32(v.w);
            *(uint4*)(sm_b + n * SS + c4 * 4) = t4;
        }
        __syncthreads();
        #pragma unroll
        for (int kk = 0; kk < 4; kk++) {
            const int kb = kk * 8;
            uint32_t af[4][4], bf[8][2];
            #pragma unroll
            for (int mt = 0; mt < 4; mt++) {
                const int r = wm * 64 + mt * 16 + lr;
                af[mt][0] = __float_as_uint(sm_a[(r + 0) * SS + kb + lc]);
                af[mt][1] = __float_as_uint(sm_a[(r + 8) * SS + kb + lc]);
                af[mt][2] = __float_as_uint(sm_a[(r + 0) * SS + kb + lc + 4]);
                af[mt][3] = __float_as_uint(sm_a[(r + 8) * SS + kb + lc + 4]);
            }
            #pragma unroll
            for (int nt = 0; nt < 8; nt++) {
                const int n = wn * 64 + nt * 8 + lr;
                bf[nt][0] = __float_as_uint(sm_b[n * SS + kb + lc]);
                bf[nt][1] = __float_as_uint(sm_b[n * SS + kb + lc + 4]);
            }
            #pragma unroll
            for (int mt = 0; mt < 4; mt++)
                #pragma unroll
                for (int nt = 0; nt < 8; nt++)
                    mma_tf32(acc[mt][nt][0], acc[mt][nt][1], acc[mt][nt][2], acc[mt][nt][3],
                             af[mt][0], af[mt][1], af[mt][2], af[mt][3],
                             bf[nt][0], bf[nt][1]);
        }
    }
    __syncthreads();
    // epilogue: (acc + be2) -> sm_m2 (tf32; cos*h1 applied next pass)
    #pragma unroll
    for (int mt = 0; mt < 4; mt++)
        #pragma unroll
        for (int half = 0; half < 2; half++) {
            const int row = wm * 64 + mt * 16 + lr + half * 8;
            #pragma unroll
            for (int nt = 0; nt < 8; nt++) {
                const int col = wn * 64 + nt * 8 + lc * 2;
                float v0 = acc[mt][nt][half * 2 + 0] + s_b2[col];
                float v1 = acc[mt][nt][half * 2 + 1] + s_b2[col + 1];
                float* p = sm_m2 + (col >> 5) * SZC + row * SS + (col & 31);
                p[0] = __uint_as_float(f2tf32(v0));
                p[1] = __uint_as_float(f2tf32(v1));
            }
        }
    __syncthreads();
    // coalesced cos * h1[src] multiply pass
    for (int i = tid; i < 128 * 64; i += 256) {
        int e = i >> 6, c4 = i & 63;
        float4 h4 = ((const float4*)(h1 + (size_t)s_src[e] * 256))[c4];
        float cs = s_cos[e];
        float* p = sm_m2 + (c4 >> 3) * SZC + e * SS + ((c4 * 4) & 31);
        p[0] = __uint_as_float(f2tf32(p[0] * cs * h4.x));
        p[1] = __uint_as_float(f2tf32(p[1] * cs * h4.y));
        p[2] = __uint_as_float(f2tf32(p[2] * cs * h4.z));
        p[3] = __uint_as_float(f2tf32(p[3] * cs * h4.w));
    }

    // ---------------- GEMM-r: m2 @ Wr2a' (K=256, N=256) ----------------
    float ac2[4][8][4];
    #pragma unroll
    for (int a = 0; a < 4; a++)
        #pragma unroll
        for (int b = 0; b < 8; b++)
            #pragma unroll
            for (int q = 0; q < 4; q++) ac2[a][b][q] = 0.f;

    for (int ch = 0; ch < 8; ch++) {
        __syncthreads();
        #pragma unroll
        for (int i = tid; i < 2048; i += 256) {
            int n = i >> 3, c4 = i & 7;
            float4 v = *(const float4*)(w2a + (size_t)n * 256 + ch * 32 + c4 * 4);
            uint4 t4; t4.x = f2tf32(v.x); t4.y = f2tf32(v.y);
            t4.z = f2tf32(v.z); t4.w = f2tf32(v.w);
            *(uint4*)(sm_b + n * SS + c4 * 4) = t4;
        }
        __syncthreads();
        const float* As = sm_m2 + ch * SZC;
        #pragma unroll
        for (int kk = 0; kk < 4; kk++) {
            const int kb = kk * 8;
            uint32_t af[4][4], bf[8][2];
            #pragma unroll
            for (int mt = 0; mt < 4; mt++) {
                const int r = wm * 64 + mt * 16 + lr;
                af[mt][0] = __float_as_uint(As[(r + 0) * SS + kb + lc]);
                af[mt][1] = __float_as_uint(As[(r + 8) * SS + kb + lc]);
                af[mt][2] = __float_as_uint(As[(r + 0) * SS + kb + lc + 4]);
                af[mt][3] = __float_as_uint(As[(r + 8) * SS + kb + lc + 4]);
            }
            #pragma unroll
            for (int nt = 0; nt < 8; nt++) {
                const int n = wn * 64 + nt * 8 + lr;
                bf[nt][0] = __float_as_uint(sm_b[n * SS + kb + lc]);
                bf[nt][1] = __float_as_uint(sm_b[n * SS + kb + lc + 4]);
            }
            #pragma unroll
            for (int mt = 0; mt < 4; mt++)
                #pragma unroll
                for (int nt = 0; nt < 8; nt++)
                    mma_tf32(ac2[mt][nt][0], ac2[mt][nt][1], ac2[mt][nt][2], ac2[mt][nt][3],
                             af[mt][0], af[mt][1], af[mt][2], af[mt][3],
                             bf[nt][0], bf[nt][1]);
        }
    }
    // epilogue: relu -> rout (DRAM)
    #pragma unroll
    for (int mt = 0; mt < 4; mt++)
        #pragma unroll
        for (int half = 0; half < 2; half++) {
            const int row = wm * 64 + mt * 16 + lr + half * 8;
            float* cp = rout + (size_t)(e0 + row) * 256;
            #pragma unroll
            for (int nt = 0; nt < 8; nt++) {
                const int col = wn * 64 + nt * 8 + lc * 2;
                float v0 = fmaxf(ac2[mt][nt][half * 2 + 0] + s_ba[col], 0.f);
                float v1 = fmaxf(ac2[mt][nt][half * 2 + 1] + s_ba[col + 1], 0.f);
                *(float2*)(cp + col) = make_float2(v0, v1);
            }
        }
}

// ---------------- generic tf32 GEMM (node GEMM + layer-2 scatter) --------------
enum { EPI_RELU = 0, EPI_SCAT = 2 };

template <int BN, int EPI>
__global__ __launch_bounds__(256, 1)
void k_mgemm(const float* __restrict__ A0, int K0,
             const float* __restrict__ A1, int K1,
             const float* __restrict__ Wt, const float* __restrict__ bias,
             float* __restrict__ C, int M, const int* __restrict__ idx) {
    constexpr int WN  = BN / 4;
    constexpr int NT  = WN / 8;
    constexpr int NB4 = BN * 8 / 256;
    constexpr int STG = (128 + BN) * SS;

    extern __shared__ float smf[];
    __shared__ float bs[BN];

    const int tid  = threadIdx.x;
    const int wid  = tid >> 5, lane = tid & 31;
    const int wm   = wid & 1, wn = wid >> 1;
    const int lr   = lane >> 2, lc = lane & 3;
    const int brow = blockIdx.x * 128;
    const int K    = K0 + K1, NC = K >> 5;

    for (int i = tid; i < BN; i += 256) bs[i] = bias[i];

    float acc[4][NT][4];
    #pragma unroll
    for (int mt = 0; mt < 4; mt++)
        #pragma unroll
        for (int nt = 0; nt < NT; nt++)
            #pragma unroll
            for (int q = 0; q < 4; q++) acc[mt][nt][q] = 0.f;

    float4 pa[4], pb[NB4];
    {
        const float* Ab; int lda, off;
        if (0 < K0) { Ab = A0; lda = K0; off = 0; } else { Ab = A1; lda = K1; off = -K0; }
        #pragma unroll
        for (int j = 0; j < 4; j++) {
            int f = tid + j * 256, row = f >> 3, c4 = f & 7;
            int gr = brow + row;
            pa[j] = (gr < M) ? *(const float4*)(Ab + (size_t)gr * lda + off + c4 * 4)
                             : make_float4(0.f, 0.f, 0.f, 0.f);
        }
        #pragma unroll
        for (int j = 0; j < NB4; j++) {
            int f = tid + j * 256, n = f >> 3, c4 = f & 7;
            pb[j] = *(const float4*)(Wt + (size_t)n * K + c4 * 4);
        }
    }

    for (int c = 0; c < NC; c++) {
        float* As = smf + (c & 1) * STG;
        float* Bs = As + 128 * SS;
        #pragma unroll
        for (int j = 0; j < 4; j++) {
            int f = tid + j * 256, row = f >> 3, c4 = f & 7;
            uint4 t; t.x = f2tf32(pa[j].x); t.y = f2tf32(pa[j].y);
            t.z = f2tf32(pa[j].z); t.w = f2tf32(pa[j].w);
            *(uint4*)(As + row * SS + c4 * 4) = t;
        }
        #pragma unroll
        for (int j = 0; j < NB4; j++) {
            int f = tid + j * 256, n = f >> 3, c4 = f & 7;
            uint4 t; t.x = f2tf32(pb[j].x); t.y = f2tf32(pb[j].y);
            t.z = f2tf32(pb[j].z); t.w = f2tf32(pb[j].w);
            *(uint4*)(Bs + n * SS + c4 * 4) = t;
        }
        __syncthreads();
        if (c + 1 < NC) {
            const int kt = (c + 1) * 32;
            const float* Ab; int lda, off;
            if (kt < K0) { Ab = A0; lda = K0; off = kt; } else { Ab = A1; lda = K1; off = kt - K0; }
            #pragma unroll
            for (int j = 0; j < 4; j++) {
                int f = tid + j * 256, row = f >> 3, c4 = f & 7;
                int gr = brow + row;
                pa[j] = (gr < M) ? *(const float4*)(Ab + (size_t)gr * lda + off + c4 * 4)
                                 : make_float4(0.f, 0.f, 0.f, 0.f);
            }
            #pragma unroll
            for (int j = 0; j < NB4; j++) {
                int f = tid + j * 256, n = f >> 3, c4 = f & 7;
                pb[j] = *(const float4*)(Wt + (size_t)n * K + kt + c4 * 4);
            }
        }
        #pragma unroll
        for (int kk = 0; kk < 4; kk++) {
            const int kb = kk * 8;
            uint32_t af[4][4], bf[NT][2];
            #pragma unroll
            for (int mt = 0; mt < 4; mt++) {
                const int r = wm * 64 + mt * 16 + lr;
                af[mt][0] = __float_as_uint(As[(r + 0) * SS + kb + lc]);
                af[mt][1] = __float_as_uint(As[(r + 8) * SS + kb + lc]);
                af[mt][2] = __float_as_uint(As[(r + 0) * SS + kb + lc + 4]);
                af[mt][3] = __float_as_uint(As[(r + 8) * SS + kb + lc + 4]);
            }
            #pragma unroll
            for (int nt = 0; nt < NT; nt++) {
                const int n = wn * WN + nt * 8 + lr;
                bf[nt][0] = __float_as_uint(Bs[n * SS + kb + lc]);
                bf[nt][1] = __float_as_uint(Bs[n * SS + kb + lc + 4]);
            }
            #pragma unroll
            for (int mt = 0; mt < 4; mt++)
                #pragma unroll
                for (int nt = 0; nt < NT; nt++)
                    mma_tf32(acc[mt][nt][0], acc[mt][nt][1], acc[mt][nt][2], acc[mt][nt][3],
                             af[mt][0], af[mt][1], af[mt][2], af[mt][3],
                             bf[nt][0], bf[nt][1]);
        }
        __syncthreads();
    }

    #pragma unroll
    for (int mt = 0; mt < 4; mt++)
        #pragma unroll
        for (int half = 0; half < 2; half++) {
            const int r = brow + wm * 64 + mt * 16 + lr + half * 8;
            if (r >= M) continue;
            float* cbase = (EPI == EPI_SCAT) ? C + (size_t)idx[r] * BN
                                             : C + (size_t)r * BN;
            #pragma unroll
            for (int nt = 0; nt < NT; nt++) {
                const int col = wn * WN + nt * 8 + lc * 2;
                float v0 = fmaxf(acc[mt][nt][half * 2 + 0] + bs[col], 0.f);
                float v1 = fmaxf(acc[mt][nt][half * 2 + 1] + bs[col + 1], 0.f);
                if (EPI == EPI_SCAT)
                    atomicAdd((float2*)(cbase + col), make_float2(v0, v1));
                else
                    *(float2*)(cbase + col) = make_float2(v0, v1);
            }
        }
}

// Final: out[N,32] = [h1 | hN] @ Wl2[512,32] + bl2
__global__ __launch_bounds__(256)
void k_final(const float* __restrict__ h1, const float* __restrict__ hN,
             const float* __restrict__ W, const float* __restrict__ bias,
             float* __restrict__ out) {
    __shared__ float sA[16][512];
    const int n0 = blockIdx.x * 16, tid = threadIdx.x;
    for (int i = tid; i < 16 * 128; i += 256) {
        int r = i >> 7, c4 = i & 127;
        const float* sp = (c4 < 64)
            ? (h1 + (size_t)(n0 + r) * HDIM + c4 * 4)
            : (hN + (size_t)(n0 + r) * HDIM + (c4 - 64) * 4);
        *(float4*)&sA[r][c4 * 4] = *(const float4*)sp;
    }
    __syncthreads();
    const int col = tid & 31, y = tid >> 5;
    float acc0 = bias[col], acc1 = bias[col];
    #pragma unroll 8
    for (int k = 0; k < 512; k++) {
        float w = W[k * 32 + col];
        acc0 += sA[y][k] * w;
        acc1 += sA[y + 8][k] * w;
    }
    out[(size_t)(n0 + y) * 32 + col]     = acc0;
    out[(size_t)(n0 + y + 8) * 32 + col] = acc1;
}

// ---------------- launch ------------------------------------------------------
extern "C" void kernel_launch(void* const* d_in, const int* in_sizes, int n_in,
                              void* d_out, int out_size) {
    const float* node_feat = (const float*)d_in[0];
    const float* edge_feat = (const float*)d_in[1];
    const int*   src       = (const int*)d_in[2];
    const int*   dst       = (const int*)d_in[3];
    const float* We1  = (const float*)d_in[4],  *be1  = (const float*)d_in[5];
    const float* Wr1a = (const float*)d_in[6],  *br1a = (const float*)d_in[7];
    const float* Wr1b = (const float*)d_in[8],  *br1b = (const float*)d_in[9];
    const float* Wl1  = (const float*)d_in[10], *bl1  = (const float*)d_in[11];
    const float* We2  = (const float*)d_in[12], *be2  = (const float*)d_in[13];
    const float* Wr2a = (const float*)d_in[14], *br2a = (const float*)d_in[15];
    const float* Wr2b = (const float*)d_in[16], *br2b = (const float*)d_in[17];
    const float* Wl2  = (const float*)d_in[18], *bl2  = (const float*)d_in[19];
    float* out = (float*)d_out;

    float *rbuf, *invv, *h1, *hN, *cnt;
    float *wr1a, *wr1b, *wl1, *we2, *wr2a, *wr2b;
    cudaGetSymbolAddress((void**)&rbuf, g_r);
    cudaGetSymbolAddress((void**)&invv, g_inv);
    cudaGetSymbolAddress((void**)&h1,   g_h1);
    cudaGetSymbolAddress((void**)&hN,   g_hN);
    cudaGetSymbolAddress((void**)&cnt,  g_cnt);
    cudaGetSymbolAddress((void**)&wr1a, g_wr1a);
    cudaGetSymbolAddress((void**)&wr1b, g_wr1b);
    cudaGetSymbolAddress((void**)&wl1,  g_wl1);
    cudaGetSymbolAddress((void**)&we2,  g_we2);
    cudaGetSymbolAddress((void**)&wr2a, g_wr2a);
    cudaGetSymbolAddress((void**)&wr2b, g_wr2b);

    const int SML1  = (9 * SZC) * 4;                       // 165888
    const int SML2A = (8 * SZC + SZC + 256 * SS) * 4;      // 202752
    const int SM256 = 2 * (128 + 256) * SS * 4;            // 110592
    cudaFuncSetAttribute(k_l1,  cudaFuncAttributeMaxDynamicSharedMemorySize, SML1);
    cudaFuncSetAttribute(k_l2a, cudaFuncAttributeMaxDynamicSharedMemorySize, SML2A);
    cudaFuncSetAttribute(k_mgemm<256, EPI_RELU>, cudaFuncAttributeMaxDynamicSharedMemorySize, SM256);
    cudaFuncSetAttribute(k_mgemm<256, EPI_SCAT>, cudaFuncAttributeMaxDynamicSharedMemorySize, SM256);

    const int ZT = 256;
    dim3 trb(32, 8);
    k_tr<<<dim3(F_IN / 32, F_IN / 32), trb>>>(Wr1a, wr1a, F_IN, F_IN);
    k_tr<<<dim3(F_IN / 32, F_IN / 32), trb>>>(Wr1b, wr1b, F_IN, F_IN);
    k_tr<<<dim3(HDIM / 32, (2 * F_IN) / 32), trb>>>(Wl1, wl1, 2 * F_IN, HDIM);
    k_tr<<<dim3(HDIM / 32, F_IN / 32), trb>>>(We2, we2, F_IN, HDIM);
    k_tr<<<dim3(HDIM / 32, HDIM / 32), trb>>>(Wr2a, wr2a, HDIM, HDIM);
    k_tr<<<dim3(HDIM / 32, HDIM / 32), trb>>>(Wr2b, wr2b, HDIM, HDIM);

    k_zero<<<(NN * F_IN + ZT - 1) / ZT, ZT>>>(hN, NN * F_IN);
    k_zero<<<(NN + ZT - 1) / ZT, ZT>>>(cnt, NN);
    k_degree<<<(EE + ZT - 1) / ZT, ZT>>>(dst, cnt, EE);

    // ---------------- layer 1 ----------------
    k_invn<<<(NN * 32 + ZT - 1) / ZT, ZT>>>(node_feat, invv, NN, F_IN);
    k_l1<<<EE / 128, 256, SML1>>>(node_feat, src, dst, invv, edge_feat,
                                  We1, be1, wr1a, br1a, wr1b, br1b, hN);
    k_div<<<(NN * F_IN + ZT - 1) / ZT, ZT>>>(hN, cnt, NN, F_IN);
    k_mgemm<256, EPI_RELU><<<(NN + 127) / 128, 256, SM256>>>(
        node_feat, F_IN, hN, F_IN, wl1, bl1, h1, NN, nullptr);

    // ---------------- layer 2 ----------------
    k_zero<<<(NN * HDIM + ZT - 1) / ZT, ZT>>>(hN, NN * HDIM);
    k_invn<<<(NN * 32 + ZT - 1) / ZT, ZT>>>(h1, invv, NN, HDIM);
    k_l2a<<<EE / 128, 256, SML2A>>>(h1, src, dst, invv, edge_feat,
                                    We1, be1, we2, be2, wr2a, br2a, rbuf);
    k_mgemm<256, EPI_SCAT><<<EE / 128, 256, SM256>>>(
        rbuf, HDIM, nullptr, 0, wr2b, br2b, hN, EE, dst);
    k_div<<<(NN * HDIM + ZT - 1) / ZT, ZT>>>(hN, cnt, NN, HDIM);

    k_final<<<NN / 16, 256>>>(h1, hN, Wl2, bl2, out);
}